// round 1
// baseline (speedup 1.0000x reference)
#include <cuda_runtime.h>
#include <cstdint>
#include <math_constants.h>

#define B_     64
#define L_     1024
#define D_     64
#define P_     2047
#define TILE_  64
#define STR_   68      // padded smem stride (floats) for d-major tiles
#define GSTR_  65      // padded stride for G (bias) tiles
#define NT_    256
#define NTILES_ (L_ / TILE_)   // 16

// Cross-kernel row statistics + mask-mode flag (static device globals: allocation-free)
__device__ int   g_mask_mode;
__device__ float g_rowmax[B_ * L_];
__device__ float g_rowsum[B_ * L_];

// ---------------------------------------------------------------------------
// Mask dtype detection. numpy bool (1B): nonzero bytes at all offsets mod 4.
// int32 0/1: nonzero only at offset 0 mod 4. float32 1.0f: nonzero at 2,3 only.
// Deterministic (reads fixed input bytes), runs inside the graph each replay.
// ---------------------------------------------------------------------------
__global__ void detect_mask_kernel(const unsigned char* __restrict__ m) {
    __shared__ int cnt[4];
    int t = threadIdx.x;
    if (t < 4) cnt[t] = 0;
    __syncthreads();
    int c0 = 0, c1 = 0, c2 = 0, c3 = 0;
    for (int i = t; i < 8192; i += blockDim.x) {
        if (m[i]) {
            int r = i & 3;
            c0 += (r == 0); c1 += (r == 1); c2 += (r == 2); c3 += (r == 3);
        }
    }
    if (c0) atomicAdd(&cnt[0], c0);
    if (c1) atomicAdd(&cnt[1], c1);
    if (c2) atomicAdd(&cnt[2], c2);
    if (c3) atomicAdd(&cnt[3], c3);
    __syncthreads();
    if (t == 0) {
        int mode = 0;  // default: 1-byte bool
        if (cnt[0] > 0 && cnt[1] == 0 && cnt[2] == 0 && cnt[3] == 0) mode = 1;            // int32
        else if (cnt[0] == 0 && cnt[1] == 0 && (cnt[2] > 0 || cnt[3] > 0)) mode = 2;      // float32
        g_mask_mode = mode;
    }
}

// 16-FMA outer product: acc[4][4] += a (col vec) * b (row vec)
#define OUTER4(acc, av, bv)                                                           \
    acc[0][0] += av.x * bv.x; acc[0][1] += av.x * bv.y;                               \
    acc[0][2] += av.x * bv.z; acc[0][3] += av.x * bv.w;                               \
    acc[1][0] += av.y * bv.x; acc[1][1] += av.y * bv.y;                               \
    acc[1][2] += av.y * bv.z; acc[1][3] += av.y * bv.w;                               \
    acc[2][0] += av.z * bv.x; acc[2][1] += av.z * bv.y;                               \
    acc[2][2] += av.z * bv.z; acc[2][3] += av.z * bv.w;                               \
    acc[3][0] += av.w * bv.x; acc[3][1] += av.w * bv.y;                               \
    acc[3][2] += av.w * bv.z; acc[3][3] += av.w * bv.w;

// transposed store of a float4 (row r, cols c4..c4+3) into d-major tile
#define STORE_T(dst, r, c4, v)                                                        \
    dst[(c4 + 0) * STR_ + (r)] = v.x;                                                 \
    dst[(c4 + 1) * STR_ + (r)] = v.y;                                                 \
    dst[(c4 + 2) * STR_ + (r)] = v.z;                                                 \
    dst[(c4 + 3) * STR_ + (r)] = v.w;

// ---------------------------------------------------------------------------
// Kernel 1: logits = Q@K^T + Hankel-bias, masked; online row max/sumexp;
// raw logits written to attn buffer.  One CTA = 64 rows x full m sweep.
// ---------------------------------------------------------------------------
__global__ __launch_bounds__(NT_, 2)
void logits_kernel(const float* __restrict__ q, const float* __restrict__ kk,
                   const float* __restrict__ pos, const char* __restrict__ maskp,
                   float* __restrict__ attn) {
    extern __shared__ float smem[];
    float* Qst  = smem;                    // [d][i], D_ x STR_, pre-scaled by 1/8
    float* QRst = Qst  + D_ * STR_;        // [d][i], reversed q rows, pre-scaled
    float* Kst  = QRst + D_ * STR_;        // [d][m] current K tile
    float* Pst  = Kst  + D_ * STR_;        // [d][p] current pos tile
    float* G0   = Pst  + D_ * STR_;        // [i][c] bias GEMM buffers
    float* G1   = G0   + TILE_ * GSTR_;
    float* sMx  = G1   + TILE_ * GSTR_;    // running row max
    float* sSm  = sMx  + TILE_;            // running row sumexp

    const int tid = threadIdx.x;
    const int ti  = tid >> 4;              // 0..15 (row group)
    const int tj  = tid & 15;              // 0..15 (col group)
    const int b   = blockIdx.y;
    const int l0  = blockIdx.x * TILE_;
    const int mode = g_mask_mode;

    const float* qb = q  + (size_t)b * L_ * D_;
    const float* kb = kk + (size_t)b * L_ * D_;
    const float* pb = pos + (size_t)b * P_ * D_;
    float* attb = attn + (size_t)b * L_ * L_;

    // --- preload Q, QR (scaled), P(l0) ---
    #pragma unroll
    for (int u = 0; u < 4; u++) {
        int f = tid + u * NT_;
        int r = f >> 4, c4 = (f & 15) << 2;
        float4 vq = *(const float4*)(qb + (size_t)(l0 + r) * D_ + c4);
        vq.x *= 0.125f; vq.y *= 0.125f; vq.z *= 0.125f; vq.w *= 0.125f;
        STORE_T(Qst, r, c4, vq);
        float4 vr = *(const float4*)(qb + (size_t)(L_ - 1 - (l0 + r)) * D_ + c4);
        vr.x *= 0.125f; vr.y *= 0.125f; vr.z *= 0.125f; vr.w *= 0.125f;
        STORE_T(QRst, r, c4, vr);
        float4 vp = *(const float4*)(pb + (size_t)(l0 + r) * D_ + c4);
        STORE_T(Pst, r, c4, vp);
    }
    if (tid < TILE_) { sMx[tid] = -CUDART_INF_F; sSm[tid] = 0.f; }
    __syncthreads();

    // --- G_0 = QR @ P(l0)^T ---
    {
        float acc[4][4] = {};
        #pragma unroll 4
        for (int d = 0; d < D_; d++) {
            float4 a  = *(const float4*)(QRst + d * STR_ + 4 * ti);
            float4 p4 = *(const float4*)(Pst  + d * STR_ + 4 * tj);
            OUTER4(acc, a, p4);
        }
        __syncthreads();
        #pragma unroll
        for (int ii = 0; ii < 4; ii++)
            #pragma unroll
            for (int jj = 0; jj < 4; jj++)
                G0[(4 * ti + ii) * GSTR_ + 4 * tj + jj] = acc[ii][jj];
    }
    // refill K(0), P(l0+64)
    #pragma unroll
    for (int u = 0; u < 4; u++) {
        int f = tid + u * NT_;
        int r = f >> 4, c4 = (f & 15) << 2;
        float4 vk = *(const float4*)(kb + (size_t)r * D_ + c4);
        STORE_T(Kst, r, c4, vk);
        int pr = l0 + TILE_ + r;
        if (pr >= P_) pr = P_ - 1;
        float4 vp = *(const float4*)(pb + (size_t)pr * D_ + c4);
        STORE_T(Pst, r, c4, vp);
    }
    __syncthreads();

    // --- main m sweep ---
    for (int t = 0; t < NTILES_; t++) {
        const int m0 = t * TILE_;
        float accS[4][4] = {};
        float accG[4][4] = {};
        #pragma unroll 4
        for (int d = 0; d < D_; d++) {
            float4 a  = *(const float4*)(Qst  + d * STR_ + 4 * ti);
            float4 k4 = *(const float4*)(Kst  + d * STR_ + 4 * tj);
            float4 rr = *(const float4*)(QRst + d * STR_ + 4 * ti);
            float4 p4 = *(const float4*)(Pst  + d * STR_ + 4 * tj);
            OUTER4(accS, a, k4);
            OUTER4(accG, rr, p4);
        }
        __syncthreads();
        float* Gc = (t & 1) ? G1 : G0;   // G_t
        float* Gn = (t & 1) ? G0 : G1;   // G_{t+1}
        #pragma unroll
        for (int ii = 0; ii < 4; ii++)
            #pragma unroll
            for (int jj = 0; jj < 4; jj++)
                Gn[(4 * ti + ii) * GSTR_ + 4 * tj + jj] = accG[ii][jj];
        if (t < NTILES_ - 1) {
            #pragma unroll
            for (int u = 0; u < 4; u++) {
                int f = tid + u * NT_;
                int r = f >> 4, c4 = (f & 15) << 2;
                float4 vk = *(const float4*)(kb + (size_t)((t + 1) * TILE_ + r) * D_ + c4);
                STORE_T(Kst, r, c4, vk);
                int pr = l0 + (t + 2) * TILE_ + r;
                if (pr >= P_) pr = P_ - 1;      // padding rows, never used by bias
                float4 vp = *(const float4*)(pb + (size_t)pr * D_ + c4);
                STORE_T(Pst, r, c4, vp);
            }
        }
        __syncthreads();

        // logits + bias + mask + online stats + store
        #pragma unroll
        for (int ii = 0; ii < 4; ii++) {
            const int i  = 4 * ti + ii;
            const int j0 = 4 * tj;
            float xs[4];
            #pragma unroll
            for (int jj = 0; jj < 4; jj++) {
                int s = i + j0 + jj;
                float bias = (s < TILE_) ? Gc[i * GSTR_ + s] : Gn[i * GSTR_ + s - TILE_];
                xs[jj] = accS[ii][jj] + bias;
            }
            size_t mrow = ((size_t)b * L_ + (l0 + i)) * L_ + m0 + j0;
            if (mode == 0) {
                unsigned int mv = *(const unsigned int*)(maskp + mrow);
                if (mv & 0x000000ffu) xs[0] = -CUDART_INF_F;
                if (mv & 0x0000ff00u) xs[1] = -CUDART_INF_F;
                if (mv & 0x00ff0000u) xs[2] = -CUDART_INF_F;
                if (mv & 0xff000000u) xs[3] = -CUDART_INF_F;
            } else if (mode == 1) {
                int4 mv = *(const int4*)((const int*)maskp + mrow);
                if (mv.x) xs[0] = -CUDART_INF_F;
                if (mv.y) xs[1] = -CUDART_INF_F;
                if (mv.z) xs[2] = -CUDART_INF_F;
                if (mv.w) xs[3] = -CUDART_INF_F;
            } else {
                float4 mv = *(const float4*)((const float*)maskp + mrow);
                if (mv.x != 0.f) xs[0] = -CUDART_INF_F;
                if (mv.y != 0.f) xs[1] = -CUDART_INF_F;
                if (mv.z != 0.f) xs[2] = -CUDART_INF_F;
                if (mv.w != 0.f) xs[3] = -CUDART_INF_F;
            }
            // half-warp (16-thread) reductions: the 16 tj threads of a row group
            // are contiguous lanes within one warp.
            float tmx = fmaxf(fmaxf(xs[0], xs[1]), fmaxf(xs[2], xs[3]));
            #pragma unroll
            for (int sft = 1; sft < 16; sft <<= 1)
                tmx = fmaxf(tmx, __shfl_xor_sync(0xffffffffu, tmx, sft));
            float oldmx = sMx[i];
            float nm  = fmaxf(oldmx, tmx);
            float nmu = (nm == -CUDART_INF_F) ? 0.f : nm;
            float es  = __expf(xs[0] - nmu) + __expf(xs[1] - nmu) +
                        __expf(xs[2] - nmu) + __expf(xs[3] - nmu);
            #pragma unroll
            for (int sft = 1; sft < 16; sft <<= 1)
                es += __shfl_xor_sync(0xffffffffu, es, sft);
            if (tj == 0) {
                sSm[i] = sSm[i] * __expf(oldmx - nmu) + es;
                sMx[i] = nm;
            }
            float4 o = make_float4(xs[0], xs[1], xs[2], xs[3]);
            *(float4*)(attb + (size_t)(l0 + i) * L_ + m0 + j0) = o;
        }
    }
    __syncthreads();
    if (tid < TILE_) {
        size_t r = (size_t)b * L_ + l0 + tid;
        g_rowmax[r] = sMx[tid];
        g_rowsum[r] = sSm[tid];
    }
}

// ---------------------------------------------------------------------------
// Kernel 2: normalize logits -> attn probabilities (written back in place),
// and O = P @ V accumulated across the m sweep.
// ---------------------------------------------------------------------------
__global__ __launch_bounds__(NT_, 2)
void pv_kernel(const float* __restrict__ v, float* __restrict__ attn,
               float* __restrict__ out) {
    __shared__ float Vs[TILE_ * STR_];    // [m][d]
    __shared__ float Pst[TILE_ * STR_];   // [m][i]  (transposed probs)

    const int tid = threadIdx.x;
    const int ti  = tid >> 4;
    const int tj  = tid & 15;
    const int b   = blockIdx.y;
    const int l0  = blockIdx.x * TILE_;
    const float* vb = v + (size_t)b * L_ * D_;
    float* attb = attn + (size_t)b * L_ * L_;

    float rmx[4], rinv[4];
    #pragma unroll
    for (int ii = 0; ii < 4; ii++) {
        size_t r = (size_t)b * L_ + l0 + 4 * ti + ii;
        float mx = g_rowmax[r];
        rmx[ii]  = (mx == -CUDART_INF_F) ? 0.f : mx;
        rinv[ii] = 1.f / g_rowsum[r];
    }

    float accO[4][4] = {};
    for (int t = 0; t < NTILES_; t++) {
        const int m0 = t * TILE_;
        #pragma unroll
        for (int u = 0; u < 4; u++) {
            int f = tid + u * NT_;
            int r = f >> 4, c4 = (f & 15) << 2;
            *(float4*)(Vs + r * STR_ + c4) =
                *(const float4*)(vb + (size_t)(m0 + r) * D_ + c4);
        }
        #pragma unroll
        for (int ii = 0; ii < 4; ii++) {
            int i = 4 * ti + ii;
            float* ap = attb + (size_t)(l0 + i) * L_ + m0 + 4 * tj;
            float4 x = *(float4*)ap;
            float4 p;
            p.x = __expf(x.x - rmx[ii]) * rinv[ii];
            p.y = __expf(x.y - rmx[ii]) * rinv[ii];
            p.z = __expf(x.z - rmx[ii]) * rinv[ii];
            p.w = __expf(x.w - rmx[ii]) * rinv[ii];
            *(float4*)ap = p;
            Pst[(4 * tj + 0) * STR_ + i] = p.x;
            Pst[(4 * tj + 1) * STR_ + i] = p.y;
            Pst[(4 * tj + 2) * STR_ + i] = p.z;
            Pst[(4 * tj + 3) * STR_ + i] = p.w;
        }
        __syncthreads();
        #pragma unroll 4
        for (int m = 0; m < TILE_; m++) {
            float4 pv = *(const float4*)(Pst + m * STR_ + 4 * ti);
            float4 vv = *(const float4*)(Vs  + m * STR_ + 4 * tj);
            OUTER4(accO, pv, vv);
        }
        __syncthreads();
    }
    #pragma unroll
    for (int ii = 0; ii < 4; ii++) {
        float4 o = make_float4(accO[ii][0], accO[ii][1], accO[ii][2], accO[ii][3]);
        *(float4*)(out + ((size_t)b * L_ + l0 + 4 * ti + ii) * D_ + 4 * tj) = o;
    }
}

// ---------------------------------------------------------------------------
extern "C" void kernel_launch(void* const* d_in, const int* in_sizes, int n_in,
                              void* d_out, int out_size) {
    const float* q   = (const float*)d_in[0];
    const float* k   = (const float*)d_in[1];
    const float* v   = (const float*)d_in[2];
    const float* pos = (const float*)d_in[3];
    const char*  msk = (const char*)d_in[4];

    float* out  = (float*)d_out;                        // (B, L, DK) first
    float* attn = out + (size_t)B_ * L_ * D_;           // then (B, L, L)

    const int smem_k1 = (4 * D_ * STR_ + 2 * TILE_ * GSTR_ + 2 * TILE_) * (int)sizeof(float);
    cudaFuncSetAttribute(logits_kernel,
                         cudaFuncAttributeMaxDynamicSharedMemorySize, smem_k1);

    detect_mask_kernel<<<1, 128>>>((const unsigned char*)msk);

    dim3 grid(NTILES_, B_);
    logits_kernel<<<grid, NT_, smem_k1>>>(q, k, pos, msk, attn);
    pv_kernel<<<grid, NT_>>>(v, attn, out);
}

// round 2
// speedup vs baseline: 1.0004x; 1.0004x over previous
#include <cuda_runtime.h>
#include <cstdint>
#include <math_constants.h>

#define B_     64
#define L_     1024
#define D_     64
#define P_     2047
#define TILE_  64
#define STR_   68      // padded smem stride (floats) for d-major tiles
#define GSTR_  65      // padded stride for G (bias) tiles
#define NT_    256
#define NTILES_ (L_ / TILE_)   // 16

// Cross-kernel row statistics + mask-mode flag (static device globals: allocation-free)
__device__ int   g_mask_mode;
__device__ float g_rowmax[B_ * L_];
__device__ float g_rowsum[B_ * L_];

// ---------------------------------------------------------------------------
// Mask dtype detection. numpy bool (1B): nonzero bytes at all offsets mod 4.
// int32 0/1: nonzero only at offset 0 mod 4. float32 1.0f: nonzero at 2,3 only.
// Deterministic (reads fixed input bytes), runs inside the graph each replay.
// ---------------------------------------------------------------------------
__global__ void detect_mask_kernel(const unsigned char* __restrict__ m) {
    __shared__ int cnt[4];
    int t = threadIdx.x;
    if (t < 4) cnt[t] = 0;
    __syncthreads();
    int c0 = 0, c1 = 0, c2 = 0, c3 = 0;
    for (int i = t; i < 8192; i += blockDim.x) {
        if (m[i]) {
            int r = i & 3;
            c0 += (r == 0); c1 += (r == 1); c2 += (r == 2); c3 += (r == 3);
        }
    }
    if (c0) atomicAdd(&cnt[0], c0);
    if (c1) atomicAdd(&cnt[1], c1);
    if (c2) atomicAdd(&cnt[2], c2);
    if (c3) atomicAdd(&cnt[3], c3);
    __syncthreads();
    if (t == 0) {
        int mode = 0;  // default: 1-byte bool
        if (cnt[0] > 0 && cnt[1] == 0 && cnt[2] == 0 && cnt[3] == 0) mode = 1;            // int32
        else if (cnt[0] == 0 && cnt[1] == 0 && (cnt[2] > 0 || cnt[3] > 0)) mode = 2;      // float32
        g_mask_mode = mode;
    }
}

// 16-FMA outer product: acc[4][4] += a (col vec) * b (row vec)
#define OUTER4(acc, av, bv)                                                           \
    acc[0][0] += av.x * bv.x; acc[0][1] += av.x * bv.y;                               \
    acc[0][2] += av.x * bv.z; acc[0][3] += av.x * bv.w;                               \
    acc[1][0] += av.y * bv.x; acc[1][1] += av.y * bv.y;                               \
    acc[1][2] += av.y * bv.z; acc[1][3] += av.y * bv.w;                               \
    acc[2][0] += av.z * bv.x; acc[2][1] += av.z * bv.y;                               \
    acc[2][2] += av.z * bv.z; acc[2][3] += av.z * bv.w;                               \
    acc[3][0] += av.w * bv.x; acc[3][1] += av.w * bv.y;                               \
    acc[3][2] += av.w * bv.z; acc[3][3] += av.w * bv.w;

// transposed store of a float4 (row r, cols c4..c4+3) into d-major tile
#define STORE_T(dst, r, c4, v)                                                        \
    dst[(c4 + 0) * STR_ + (r)] = v.x;                                                 \
    dst[(c4 + 1) * STR_ + (r)] = v.y;                                                 \
    dst[(c4 + 2) * STR_ + (r)] = v.z;                                                 \
    dst[(c4 + 3) * STR_ + (r)] = v.w;

// ---------------------------------------------------------------------------
// Kernel 1: logits = Q@K^T + Hankel-bias, masked; online row max/sumexp;
// raw logits written to attn buffer.  One CTA = 64 rows x full m sweep.
// ---------------------------------------------------------------------------
__global__ __launch_bounds__(NT_, 2)
void logits_kernel(const float* __restrict__ q, const float* __restrict__ kk,
                   const float* __restrict__ pos, const char* __restrict__ maskp,
                   float* __restrict__ attn) {
    extern __shared__ float smem[];
    float* Qst  = smem;                    // [d][i], D_ x STR_, pre-scaled by 1/8
    float* QRst = Qst  + D_ * STR_;        // [d][i], reversed q rows, pre-scaled
    float* Kst  = QRst + D_ * STR_;        // [d][m] current K tile
    float* Pst  = Kst  + D_ * STR_;        // [d][p] current pos tile
    float* G0   = Pst  + D_ * STR_;        // [i][c] bias GEMM buffers
    float* G1   = G0   + TILE_ * GSTR_;
    float* sMx  = G1   + TILE_ * GSTR_;    // running row max
    float* sSm  = sMx  + TILE_;            // running row sumexp

    const int tid = threadIdx.x;
    const int ti  = tid >> 4;              // 0..15 (row group)
    const int tj  = tid & 15;              // 0..15 (col group)
    const int b   = blockIdx.y;
    const int l0  = blockIdx.x * TILE_;
    const int mode = g_mask_mode;

    const float* qb = q  + (size_t)b * L_ * D_;
    const float* kb = kk + (size_t)b * L_ * D_;
    const float* pb = pos + (size_t)b * P_ * D_;
    float* attb = attn + (size_t)b * L_ * L_;

    // --- preload Q, QR (scaled), P(l0) ---
    #pragma unroll
    for (int u = 0; u < 4; u++) {
        int f = tid + u * NT_;
        int r = f >> 4, c4 = (f & 15) << 2;
        float4 vq = *(const float4*)(qb + (size_t)(l0 + r) * D_ + c4);
        vq.x *= 0.125f; vq.y *= 0.125f; vq.z *= 0.125f; vq.w *= 0.125f;
        STORE_T(Qst, r, c4, vq);
        float4 vr = *(const float4*)(qb + (size_t)(L_ - 1 - (l0 + r)) * D_ + c4);
        vr.x *= 0.125f; vr.y *= 0.125f; vr.z *= 0.125f; vr.w *= 0.125f;
        STORE_T(QRst, r, c4, vr);
        float4 vp = *(const float4*)(pb + (size_t)(l0 + r) * D_ + c4);
        STORE_T(Pst, r, c4, vp);
    }
    if (tid < TILE_) { sMx[tid] = -CUDART_INF_F; sSm[tid] = 0.f; }
    __syncthreads();

    // --- G_0 = QR @ P(l0)^T ---
    {
        float acc[4][4] = {};
        #pragma unroll 4
        for (int d = 0; d < D_; d++) {
            float4 a  = *(const float4*)(QRst + d * STR_ + 4 * ti);
            float4 p4 = *(const float4*)(Pst  + d * STR_ + 4 * tj);
            OUTER4(acc, a, p4);
        }
        __syncthreads();
        #pragma unroll
        for (int ii = 0; ii < 4; ii++)
            #pragma unroll
            for (int jj = 0; jj < 4; jj++)
                G0[(4 * ti + ii) * GSTR_ + 4 * tj + jj] = acc[ii][jj];
    }
    // refill K(0), P(l0+64)
    #pragma unroll
    for (int u = 0; u < 4; u++) {
        int f = tid + u * NT_;
        int r = f >> 4, c4 = (f & 15) << 2;
        float4 vk = *(const float4*)(kb + (size_t)r * D_ + c4);
        STORE_T(Kst, r, c4, vk);
        int pr = l0 + TILE_ + r;
        if (pr >= P_) pr = P_ - 1;
        float4 vp = *(const float4*)(pb + (size_t)pr * D_ + c4);
        STORE_T(Pst, r, c4, vp);
    }
    __syncthreads();

    // --- main m sweep ---
    for (int t = 0; t < NTILES_; t++) {
        const int m0 = t * TILE_;
        float accS[4][4] = {};
        float accG[4][4] = {};
        #pragma unroll 4
        for (int d = 0; d < D_; d++) {
            float4 a  = *(const float4*)(Qst  + d * STR_ + 4 * ti);
            float4 k4 = *(const float4*)(Kst  + d * STR_ + 4 * tj);
            float4 rr = *(const float4*)(QRst + d * STR_ + 4 * ti);
            float4 p4 = *(const float4*)(Pst  + d * STR_ + 4 * tj);
            OUTER4(accS, a, k4);
            OUTER4(accG, rr, p4);
        }
        __syncthreads();
        float* Gc = (t & 1) ? G1 : G0;   // G_t
        float* Gn = (t & 1) ? G0 : G1;   // G_{t+1}
        #pragma unroll
        for (int ii = 0; ii < 4; ii++)
            #pragma unroll
            for (int jj = 0; jj < 4; jj++)
                Gn[(4 * ti + ii) * GSTR_ + 4 * tj + jj] = accG[ii][jj];
        if (t < NTILES_ - 1) {
            #pragma unroll
            for (int u = 0; u < 4; u++) {
                int f = tid + u * NT_;
                int r = f >> 4, c4 = (f & 15) << 2;
                float4 vk = *(const float4*)(kb + (size_t)((t + 1) * TILE_ + r) * D_ + c4);
                STORE_T(Kst, r, c4, vk);
                int pr = l0 + (t + 2) * TILE_ + r;
                if (pr >= P_) pr = P_ - 1;      // padding rows, never used by bias
                float4 vp = *(const float4*)(pb + (size_t)pr * D_ + c4);
                STORE_T(Pst, r, c4, vp);
            }
        }
        __syncthreads();

        // logits + bias + mask + online stats + store
        #pragma unroll
        for (int ii = 0; ii < 4; ii++) {
            const int i  = 4 * ti + ii;
            const int j0 = 4 * tj;
            float xs[4];
            #pragma unroll
            for (int jj = 0; jj < 4; jj++) {
                int s = i + j0 + jj;
                float bias = (s < TILE_) ? Gc[i * GSTR_ + s] : Gn[i * GSTR_ + s - TILE_];
                xs[jj] = accS[ii][jj] + bias;
            }
            size_t mrow = ((size_t)b * L_ + (l0 + i)) * L_ + m0 + j0;
            if (mode == 0) {
                unsigned int mv = *(const unsigned int*)(maskp + mrow);
                if (mv & 0x000000ffu) xs[0] = -CUDART_INF_F;
                if (mv & 0x0000ff00u) xs[1] = -CUDART_INF_F;
                if (mv & 0x00ff0000u) xs[2] = -CUDART_INF_F;
                if (mv & 0xff000000u) xs[3] = -CUDART_INF_F;
            } else if (mode == 1) {
                int4 mv = *(const int4*)((const int*)maskp + mrow);
                if (mv.x) xs[0] = -CUDART_INF_F;
                if (mv.y) xs[1] = -CUDART_INF_F;
                if (mv.z) xs[2] = -CUDART_INF_F;
                if (mv.w) xs[3] = -CUDART_INF_F;
            } else {
                float4 mv = *(const float4*)((const float*)maskp + mrow);
                if (mv.x != 0.f) xs[0] = -CUDART_INF_F;
                if (mv.y != 0.f) xs[1] = -CUDART_INF_F;
                if (mv.z != 0.f) xs[2] = -CUDART_INF_F;
                if (mv.w != 0.f) xs[3] = -CUDART_INF_F;
            }
            // half-warp (16-thread) reductions: the 16 tj threads of a row group
            // are contiguous lanes within one warp.
            float tmx = fmaxf(fmaxf(xs[0], xs[1]), fmaxf(xs[2], xs[3]));
            #pragma unroll
            for (int sft = 1; sft < 16; sft <<= 1)
                tmx = fmaxf(tmx, __shfl_xor_sync(0xffffffffu, tmx, sft));
            float oldmx = sMx[i];
            float nm  = fmaxf(oldmx, tmx);
            float nmu = (nm == -CUDART_INF_F) ? 0.f : nm;
            float es  = __expf(xs[0] - nmu) + __expf(xs[1] - nmu) +
                        __expf(xs[2] - nmu) + __expf(xs[3] - nmu);
            #pragma unroll
            for (int sft = 1; sft < 16; sft <<= 1)
                es += __shfl_xor_sync(0xffffffffu, es, sft);
            if (tj == 0) {
                sSm[i] = sSm[i] * __expf(oldmx - nmu) + es;
                sMx[i] = nm;
            }
            float4 o = make_float4(xs[0], xs[1], xs[2], xs[3]);
            *(float4*)(attb + (size_t)(l0 + i) * L_ + m0 + j0) = o;
        }
    }
    __syncthreads();
    if (tid < TILE_) {
        size_t r = (size_t)b * L_ + l0 + tid;
        g_rowmax[r] = sMx[tid];
        g_rowsum[r] = sSm[tid];
    }
}

// ---------------------------------------------------------------------------
// Kernel 2: normalize logits -> attn probabilities (written back in place),
// and O = P @ V accumulated across the m sweep.
// ---------------------------------------------------------------------------
__global__ __launch_bounds__(NT_, 2)
void pv_kernel(const float* __restrict__ v, float* __restrict__ attn,
               float* __restrict__ out) {
    __shared__ float Vs[TILE_ * STR_];    // [m][d]
    __shared__ float Pst[TILE_ * STR_];   // [m][i]  (transposed probs)

    const int tid = threadIdx.x;
    const int ti  = tid >> 4;
    const int tj  = tid & 15;
    const int b   = blockIdx.y;
    const int l0  = blockIdx.x * TILE_;
    const float* vb = v + (size_t)b * L_ * D_;
    float* attb = attn + (size_t)b * L_ * L_;

    float rmx[4], rinv[4];
    #pragma unroll
    for (int ii = 0; ii < 4; ii++) {
        size_t r = (size_t)b * L_ + l0 + 4 * ti + ii;
        float mx = g_rowmax[r];
        rmx[ii]  = (mx == -CUDART_INF_F) ? 0.f : mx;
        rinv[ii] = 1.f / g_rowsum[r];
    }

    float accO[4][4] = {};
    for (int t = 0; t < NTILES_; t++) {
        const int m0 = t * TILE_;
        #pragma unroll
        for (int u = 0; u < 4; u++) {
            int f = tid + u * NT_;
            int r = f >> 4, c4 = (f & 15) << 2;
            *(float4*)(Vs + r * STR_ + c4) =
                *(const float4*)(vb + (size_t)(m0 + r) * D_ + c4);
        }
        #pragma unroll
        for (int ii = 0; ii < 4; ii++) {
            int i = 4 * ti + ii;
            float* ap = attb + (size_t)(l0 + i) * L_ + m0 + 4 * tj;
            float4 x = *(float4*)ap;
            float4 p;
            p.x = __expf(x.x - rmx[ii]) * rinv[ii];
            p.y = __expf(x.y - rmx[ii]) * rinv[ii];
            p.z = __expf(x.z - rmx[ii]) * rinv[ii];
            p.w = __expf(x.w - rmx[ii]) * rinv[ii];
            *(float4*)ap = p;
            Pst[(4 * tj + 0) * STR_ + i] = p.x;
            Pst[(4 * tj + 1) * STR_ + i] = p.y;
            Pst[(4 * tj + 2) * STR_ + i] = p.z;
            Pst[(4 * tj + 3) * STR_ + i] = p.w;
        }
        __syncthreads();
        #pragma unroll 4
        for (int m = 0; m < TILE_; m++) {
            float4 pv = *(const float4*)(Pst + m * STR_ + 4 * ti);
            float4 vv = *(const float4*)(Vs  + m * STR_ + 4 * tj);
            OUTER4(accO, pv, vv);
        }
        __syncthreads();
    }
    #pragma unroll
    for (int ii = 0; ii < 4; ii++) {
        float4 o = make_float4(accO[ii][0], accO[ii][1], accO[ii][2], accO[ii][3]);
        *(float4*)(out + ((size_t)b * L_ + l0 + 4 * ti + ii) * D_ + 4 * tj) = o;
    }
}

// ---------------------------------------------------------------------------
extern "C" void kernel_launch(void* const* d_in, const int* in_sizes, int n_in,
                              void* d_out, int out_size) {
    const float* q   = (const float*)d_in[0];
    const float* k   = (const float*)d_in[1];
    const float* v   = (const float*)d_in[2];
    const float* pos = (const float*)d_in[3];
    const char*  msk = (const char*)d_in[4];

    float* out  = (float*)d_out;                        // (B, L, DK) first
    float* attn = out + (size_t)B_ * L_ * D_;           // then (B, L, L)

    const int smem_k1 = (4 * D_ * STR_ + 2 * TILE_ * GSTR_ + 2 * TILE_) * (int)sizeof(float);
    cudaFuncSetAttribute(logits_kernel,
                         cudaFuncAttributeMaxDynamicSharedMemorySize, smem_k1);

    detect_mask_kernel<<<1, 128>>>((const unsigned char*)msk);

    dim3 grid(NTILES_, B_);
    logits_kernel<<<grid, NT_, smem_k1>>>(q, k, pos, msk, attn);
    pv_kernel<<<grid, NT_>>>(v, attn, out);
}

// round 3
// speedup vs baseline: 1.0004x; 1.0001x over previous
#include <cuda_runtime.h>
#include <cstdint>
#include <math_constants.h>

#define B_     64
#define L_     1024
#define D_     64
#define P_     2047
#define TILE_  64
#define STR_   68      // padded smem stride (floats) for d-major tiles
#define GSTR_  65      // padded stride for G (bias) tiles
#define NT_    256
#define NTILES_ (L_ / TILE_)   // 16

// Cross-kernel row statistics + mask-mode flag (static device globals: allocation-free)
__device__ int   g_mask_mode;
__device__ float g_rowmax[B_ * L_];
__device__ float g_rowsum[B_ * L_];

// ---------------------------------------------------------------------------
// Mask dtype detection. numpy bool (1B): nonzero bytes at all offsets mod 4.
// int32 0/1: nonzero only at offset 0 mod 4. float32 1.0f: nonzero at 2,3 only.
// Deterministic (reads fixed input bytes), runs inside the graph each replay.
// ---------------------------------------------------------------------------
__global__ void detect_mask_kernel(const unsigned char* __restrict__ m) {
    __shared__ int cnt[4];
    int t = threadIdx.x;
    if (t < 4) cnt[t] = 0;
    __syncthreads();
    int c0 = 0, c1 = 0, c2 = 0, c3 = 0;
    for (int i = t; i < 8192; i += blockDim.x) {
        if (m[i]) {
            int r = i & 3;
            c0 += (r == 0); c1 += (r == 1); c2 += (r == 2); c3 += (r == 3);
        }
    }
    if (c0) atomicAdd(&cnt[0], c0);
    if (c1) atomicAdd(&cnt[1], c1);
    if (c2) atomicAdd(&cnt[2], c2);
    if (c3) atomicAdd(&cnt[3], c3);
    __syncthreads();
    if (t == 0) {
        int mode = 0;  // default: 1-byte bool
        if (cnt[0] > 0 && cnt[1] == 0 && cnt[2] == 0 && cnt[3] == 0) mode = 1;            // int32
        else if (cnt[0] == 0 && cnt[1] == 0 && (cnt[2] > 0 || cnt[3] > 0)) mode = 2;      // float32
        g_mask_mode = mode;
    }
}

// 16-FMA outer product: acc[4][4] += a (col vec) * b (row vec)
#define OUTER4(acc, av, bv)                                                           \
    acc[0][0] += av.x * bv.x; acc[0][1] += av.x * bv.y;                               \
    acc[0][2] += av.x * bv.z; acc[0][3] += av.x * bv.w;                               \
    acc[1][0] += av.y * bv.x; acc[1][1] += av.y * bv.y;                               \
    acc[1][2] += av.y * bv.z; acc[1][3] += av.y * bv.w;                               \
    acc[2][0] += av.z * bv.x; acc[2][1] += av.z * bv.y;                               \
    acc[2][2] += av.z * bv.z; acc[2][3] += av.z * bv.w;                               \
    acc[3][0] += av.w * bv.x; acc[3][1] += av.w * bv.y;                               \
    acc[3][2] += av.w * bv.z; acc[3][3] += av.w * bv.w;

// transposed store of a float4 (row r, cols c4..c4+3) into d-major tile
#define STORE_T(dst, r, c4, v)                                                        \
    dst[(c4 + 0) * STR_ + (r)] = v.x;                                                 \
    dst[(c4 + 1) * STR_ + (r)] = v.y;                                                 \
    dst[(c4 + 2) * STR_ + (r)] = v.z;                                                 \
    dst[(c4 + 3) * STR_ + (r)] = v.w;

// ---------------------------------------------------------------------------
// Kernel 1: logits = Q@K^T + Hankel-bias, masked; online row max/sumexp;
// raw logits written to attn buffer.  One CTA = 64 rows x full m sweep.
// ---------------------------------------------------------------------------
__global__ __launch_bounds__(NT_, 2)
void logits_kernel(const float* __restrict__ q, const float* __restrict__ kk,
                   const float* __restrict__ pos, const char* __restrict__ maskp,
                   float* __restrict__ attn) {
    extern __shared__ float smem[];
    float* Qst  = smem;                    // [d][i], D_ x STR_, pre-scaled by 1/8
    float* QRst = Qst  + D_ * STR_;        // [d][i], reversed q rows, pre-scaled
    float* Kst  = QRst + D_ * STR_;        // [d][m] current K tile
    float* Pst  = Kst  + D_ * STR_;        // [d][p] current pos tile
    float* G0   = Pst  + D_ * STR_;        // [i][c] bias GEMM buffers
    float* G1   = G0   + TILE_ * GSTR_;
    float* sMx  = G1   + TILE_ * GSTR_;    // running row max
    float* sSm  = sMx  + TILE_;            // running row sumexp

    const int tid = threadIdx.x;
    const int ti  = tid >> 4;              // 0..15 (row group)
    const int tj  = tid & 15;              // 0..15 (col group)
    const int b   = blockIdx.y;
    const int l0  = blockIdx.x * TILE_;
    const int mode = g_mask_mode;

    const float* qb = q  + (size_t)b * L_ * D_;
    const float* kb = kk + (size_t)b * L_ * D_;
    const float* pb = pos + (size_t)b * P_ * D_;
    float* attb = attn + (size_t)b * L_ * L_;

    // --- preload Q, QR (scaled), P(l0) ---
    #pragma unroll
    for (int u = 0; u < 4; u++) {
        int f = tid + u * NT_;
        int r = f >> 4, c4 = (f & 15) << 2;
        float4 vq = *(const float4*)(qb + (size_t)(l0 + r) * D_ + c4);
        vq.x *= 0.125f; vq.y *= 0.125f; vq.z *= 0.125f; vq.w *= 0.125f;
        STORE_T(Qst, r, c4, vq);
        float4 vr = *(const float4*)(qb + (size_t)(L_ - 1 - (l0 + r)) * D_ + c4);
        vr.x *= 0.125f; vr.y *= 0.125f; vr.z *= 0.125f; vr.w *= 0.125f;
        STORE_T(QRst, r, c4, vr);
        float4 vp = *(const float4*)(pb + (size_t)(l0 + r) * D_ + c4);
        STORE_T(Pst, r, c4, vp);
    }
    if (tid < TILE_) { sMx[tid] = -CUDART_INF_F; sSm[tid] = 0.f; }
    __syncthreads();

    // --- G_0 = QR @ P(l0)^T ---
    {
        float acc[4][4] = {};
        #pragma unroll 4
        for (int d = 0; d < D_; d++) {
            float4 a  = *(const float4*)(QRst + d * STR_ + 4 * ti);
            float4 p4 = *(const float4*)(Pst  + d * STR_ + 4 * tj);
            OUTER4(acc, a, p4);
        }
        __syncthreads();
        #pragma unroll
        for (int ii = 0; ii < 4; ii++)
            #pragma unroll
            for (int jj = 0; jj < 4; jj++)
                G0[(4 * ti + ii) * GSTR_ + 4 * tj + jj] = acc[ii][jj];
    }
    // refill K(0), P(l0+64)
    #pragma unroll
    for (int u = 0; u < 4; u++) {
        int f = tid + u * NT_;
        int r = f >> 4, c4 = (f & 15) << 2;
        float4 vk = *(const float4*)(kb + (size_t)r * D_ + c4);
        STORE_T(Kst, r, c4, vk);
        int pr = l0 + TILE_ + r;
        if (pr >= P_) pr = P_ - 1;
        float4 vp = *(const float4*)(pb + (size_t)pr * D_ + c4);
        STORE_T(Pst, r, c4, vp);
    }
    __syncthreads();

    // --- main m sweep ---
    for (int t = 0; t < NTILES_; t++) {
        const int m0 = t * TILE_;
        float accS[4][4] = {};
        float accG[4][4] = {};
        #pragma unroll 4
        for (int d = 0; d < D_; d++) {
            float4 a  = *(const float4*)(Qst  + d * STR_ + 4 * ti);
            float4 k4 = *(const float4*)(Kst  + d * STR_ + 4 * tj);
            float4 rr = *(const float4*)(QRst + d * STR_ + 4 * ti);
            float4 p4 = *(const float4*)(Pst  + d * STR_ + 4 * tj);
            OUTER4(accS, a, k4);
            OUTER4(accG, rr, p4);
        }
        __syncthreads();
        float* Gc = (t & 1) ? G1 : G0;   // G_t
        float* Gn = (t & 1) ? G0 : G1;   // G_{t+1}
        #pragma unroll
        for (int ii = 0; ii < 4; ii++)
            #pragma unroll
            for (int jj = 0; jj < 4; jj++)
                Gn[(4 * ti + ii) * GSTR_ + 4 * tj + jj] = accG[ii][jj];
        if (t < NTILES_ - 1) {
            #pragma unroll
            for (int u = 0; u < 4; u++) {
                int f = tid + u * NT_;
                int r = f >> 4, c4 = (f & 15) << 2;
                float4 vk = *(const float4*)(kb + (size_t)((t + 1) * TILE_ + r) * D_ + c4);
                STORE_T(Kst, r, c4, vk);
                int pr = l0 + (t + 2) * TILE_ + r;
                if (pr >= P_) pr = P_ - 1;      // padding rows, never used by bias
                float4 vp = *(const float4*)(pb + (size_t)pr * D_ + c4);
                STORE_T(Pst, r, c4, vp);
            }
        }
        __syncthreads();

        // logits + bias + mask + online stats + store
        #pragma unroll
        for (int ii = 0; ii < 4; ii++) {
            const int i  = 4 * ti + ii;
            const int j0 = 4 * tj;
            float xs[4];
            #pragma unroll
            for (int jj = 0; jj < 4; jj++) {
                int s = i + j0 + jj;
                float bias = (s < TILE_) ? Gc[i * GSTR_ + s] : Gn[i * GSTR_ + s - TILE_];
                xs[jj] = accS[ii][jj] + bias;
            }
            size_t mrow = ((size_t)b * L_ + (l0 + i)) * L_ + m0 + j0;
            if (mode == 0) {
                unsigned int mv = *(const unsigned int*)(maskp + mrow);
                if (mv & 0x000000ffu) xs[0] = -CUDART_INF_F;
                if (mv & 0x0000ff00u) xs[1] = -CUDART_INF_F;
                if (mv & 0x00ff0000u) xs[2] = -CUDART_INF_F;
                if (mv & 0xff000000u) xs[3] = -CUDART_INF_F;
            } else if (mode == 1) {
                int4 mv = *(const int4*)((const int*)maskp + mrow);
                if (mv.x) xs[0] = -CUDART_INF_F;
                if (mv.y) xs[1] = -CUDART_INF_F;
                if (mv.z) xs[2] = -CUDART_INF_F;
                if (mv.w) xs[3] = -CUDART_INF_F;
            } else {
                float4 mv = *(const float4*)((const float*)maskp + mrow);
                if (mv.x != 0.f) xs[0] = -CUDART_INF_F;
                if (mv.y != 0.f) xs[1] = -CUDART_INF_F;
                if (mv.z != 0.f) xs[2] = -CUDART_INF_F;
                if (mv.w != 0.f) xs[3] = -CUDART_INF_F;
            }
            // half-warp (16-thread) reductions: the 16 tj threads of a row group
            // are contiguous lanes within one warp.
            float tmx = fmaxf(fmaxf(xs[0], xs[1]), fmaxf(xs[2], xs[3]));
            #pragma unroll
            for (int sft = 1; sft < 16; sft <<= 1)
                tmx = fmaxf(tmx, __shfl_xor_sync(0xffffffffu, tmx, sft));
            float oldmx = sMx[i];
            float nm  = fmaxf(oldmx, tmx);
            float nmu = (nm == -CUDART_INF_F) ? 0.f : nm;
            float es  = __expf(xs[0] - nmu) + __expf(xs[1] - nmu) +
                        __expf(xs[2] - nmu) + __expf(xs[3] - nmu);
            #pragma unroll
            for (int sft = 1; sft < 16; sft <<= 1)
                es += __shfl_xor_sync(0xffffffffu, es, sft);
            if (tj == 0) {
                sSm[i] = sSm[i] * __expf(oldmx - nmu) + es;
                sMx[i] = nm;
            }
            float4 o = make_float4(xs[0], xs[1], xs[2], xs[3]);
            *(float4*)(attb + (size_t)(l0 + i) * L_ + m0 + j0) = o;
        }
    }
    __syncthreads();
    if (tid < TILE_) {
        size_t r = (size_t)b * L_ + l0 + tid;
        g_rowmax[r] = sMx[tid];
        g_rowsum[r] = sSm[tid];
    }
}

// ---------------------------------------------------------------------------
// Kernel 2: normalize logits -> attn probabilities (written back in place),
// and O = P @ V accumulated across the m sweep.
// ---------------------------------------------------------------------------
__global__ __launch_bounds__(NT_, 2)
void pv_kernel(const float* __restrict__ v, float* __restrict__ attn,
               float* __restrict__ out) {
    __shared__ float Vs[TILE_ * STR_];    // [m][d]
    __shared__ float Pst[TILE_ * STR_];   // [m][i]  (transposed probs)

    const int tid = threadIdx.x;
    const int ti  = tid >> 4;
    const int tj  = tid & 15;
    const int b   = blockIdx.y;
    const int l0  = blockIdx.x * TILE_;
    const float* vb = v + (size_t)b * L_ * D_;
    float* attb = attn + (size_t)b * L_ * L_;

    float rmx[4], rinv[4];
    #pragma unroll
    for (int ii = 0; ii < 4; ii++) {
        size_t r = (size_t)b * L_ + l0 + 4 * ti + ii;
        float mx = g_rowmax[r];
        rmx[ii]  = (mx == -CUDART_INF_F) ? 0.f : mx;
        rinv[ii] = 1.f / g_rowsum[r];
    }

    float accO[4][4] = {};
    for (int t = 0; t < NTILES_; t++) {
        const int m0 = t * TILE_;
        #pragma unroll
        for (int u = 0; u < 4; u++) {
            int f = tid + u * NT_;
            int r = f >> 4, c4 = (f & 15) << 2;
            *(float4*)(Vs + r * STR_ + c4) =
                *(const float4*)(vb + (size_t)(m0 + r) * D_ + c4);
        }
        #pragma unroll
        for (int ii = 0; ii < 4; ii++) {
            int i = 4 * ti + ii;
            float* ap = attb + (size_t)(l0 + i) * L_ + m0 + 4 * tj;
            float4 x = *(float4*)ap;
            float4 p;
            p.x = __expf(x.x - rmx[ii]) * rinv[ii];
            p.y = __expf(x.y - rmx[ii]) * rinv[ii];
            p.z = __expf(x.z - rmx[ii]) * rinv[ii];
            p.w = __expf(x.w - rmx[ii]) * rinv[ii];
            *(float4*)ap = p;
            Pst[(4 * tj + 0) * STR_ + i] = p.x;
            Pst[(4 * tj + 1) * STR_ + i] = p.y;
            Pst[(4 * tj + 2) * STR_ + i] = p.z;
            Pst[(4 * tj + 3) * STR_ + i] = p.w;
        }
        __syncthreads();
        #pragma unroll 4
        for (int m = 0; m < TILE_; m++) {
            float4 pv = *(const float4*)(Pst + m * STR_ + 4 * ti);
            float4 vv = *(const float4*)(Vs  + m * STR_ + 4 * tj);
            OUTER4(accO, pv, vv);
        }
        __syncthreads();
    }
    #pragma unroll
    for (int ii = 0; ii < 4; ii++) {
        float4 o = make_float4(accO[ii][0], accO[ii][1], accO[ii][2], accO[ii][3]);
        *(float4*)(out + ((size_t)b * L_ + l0 + 4 * ti + ii) * D_ + 4 * tj) = o;
    }
}

// ---------------------------------------------------------------------------
extern "C" void kernel_launch(void* const* d_in, const int* in_sizes, int n_in,
                              void* d_out, int out_size) {
    const float* q   = (const float*)d_in[0];
    const float* k   = (const float*)d_in[1];
    const float* v   = (const float*)d_in[2];
    const float* pos = (const float*)d_in[3];
    const char*  msk = (const char*)d_in[4];

    float* out  = (float*)d_out;                        // (B, L, DK) first
    float* attn = out + (size_t)B_ * L_ * D_;           // then (B, L, L)

    const int smem_k1 = (4 * D_ * STR_ + 2 * TILE_ * GSTR_ + 2 * TILE_) * (int)sizeof(float);
    cudaFuncSetAttribute(logits_kernel,
                         cudaFuncAttributeMaxDynamicSharedMemorySize, smem_k1);

    detect_mask_kernel<<<1, 128>>>((const unsigned char*)msk);

    dim3 grid(NTILES_, B_);
    logits_kernel<<<grid, NT_, smem_k1>>>(q, k, pos, msk, attn);
    pv_kernel<<<grid, NT_>>>(v, attn, out);
}

// round 5
// speedup vs baseline: 1.6843x; 1.6836x over previous
#include <cuda_runtime.h>
#include <cuda_bf16.h>
#include <cstdint>
#include <math_constants.h>

#define B_ 64
#define L_ 1024
#define P_ 2047
#define SB 72          // smem tile stride (bf16 elems) = 144B rows
#define GS 68          // G buffer stride (floats)
#define NS 16

#define TILEB (64 * SB * 2)
#define O_QH 0
#define O_QL (O_QH + TILEB)
#define O_RH (O_QL + TILEB)
#define O_RL (O_RH + TILEB)
#define O_KH (O_RL + TILEB)
#define O_KL (O_KH + TILEB)
#define O_PH (O_KL + TILEB)
#define O_PL (O_PH + TILEB)
#define O_G  (O_PL + TILEB)
#define GSZ  (64 * GS)
#define O_ST (O_G + 2 * GSZ * 4)
#define O_MC (O_ST + 64 * 2 * 8)
#define SMEMB (O_MC + 16)

__device__ __forceinline__ uint32_t smem_u32(const void* p) {
    uint32_t a;
    asm("{ .reg .u64 t; cvta.to.shared.u64 t, %1; cvt.u32.u64 %0, t; }" : "=r"(a) : "l"(p));
    return a;
}

#define LDSM4(r, a) \
    asm volatile("ldmatrix.sync.aligned.m8n8.x4.shared.b16 {%0,%1,%2,%3}, [%4];" \
        : "=r"((r)[0]), "=r"((r)[1]), "=r"((r)[2]), "=r"((r)[3]) : "r"(a))
#define LDSM2(r, a) \
    asm volatile("ldmatrix.sync.aligned.m8n8.x2.shared.b16 {%0,%1}, [%2];" \
        : "=r"((r)[0]), "=r"((r)[1]) : "r"(a))
#define LDSM2T(r, a) \
    asm volatile("ldmatrix.sync.aligned.m8n8.x2.trans.shared.b16 {%0,%1}, [%2];" \
        : "=r"((r)[0]), "=r"((r)[1]) : "r"(a))
#define MMA(c, a, b) \
    asm volatile("mma.sync.aligned.m16n8k16.row.col.f32.bf16.bf16.f32 " \
        "{%0,%1,%2,%3}, {%4,%5,%6,%7}, {%8,%9}, {%0,%1,%2,%3};" \
        : "+f"((c)[0]), "+f"((c)[1]), "+f"((c)[2]), "+f"((c)[3]) \
        : "r"((a)[0]), "r"((a)[1]), "r"((a)[2]), "r"((a)[3]), "r"((b)[0]), "r"((b)[1]))

__device__ __forceinline__ uint32_t pk2(float a, float b) {
    return (uint32_t)__bfloat16_as_ushort(__float2bfloat16(a)) |
           ((uint32_t)__bfloat16_as_ushort(__float2bfloat16(b)) << 16);
}
// split float4 -> bf16 hi/lo (4 each), store 8B into smem tiles at elem offset eo
__device__ __forceinline__ void spl(char* sm, int offH, int offL, int eo, float4 v) {
    float hx = __bfloat162float(__float2bfloat16(v.x));
    float hy = __bfloat162float(__float2bfloat16(v.y));
    float hz = __bfloat162float(__float2bfloat16(v.z));
    float hw = __bfloat162float(__float2bfloat16(v.w));
    *(uint2*)(sm + offH + eo * 2) = make_uint2(pk2(v.x, v.y), pk2(v.z, v.w));
    *(uint2*)(sm + offL + eo * 2) =
        make_uint2(pk2(v.x - hx, v.y - hy), pk2(v.z - hz, v.w - hw));
}

__device__ __forceinline__ void merge_ms(float& m, float& s, float om, float os) {
    float nm = fmaxf(m, om);
    float base = (nm == -CUDART_INF_F) ? 0.f : nm;
    s = s * __expf(m - base) + os * __expf(om - base);
    m = nm;
}

__global__ __launch_bounds__(256)
void fused_mma_kernel(const float* __restrict__ q, const float* __restrict__ kk,
                      const float* __restrict__ v, const float* __restrict__ pos,
                      const char* __restrict__ maskp, float* __restrict__ out,
                      float* __restrict__ attn) {
    extern __shared__ char sm[];
    const uint32_t sb = smem_u32(sm);
    const int tid = threadIdx.x;
    const int lane = tid & 31, w = tid >> 5;
    const int wr = w & 3, wc = w >> 2;
    const int b = blockIdx.y, l0 = blockIdx.x * 64;

    const float* qb = q + (size_t)b * L_ * 64;
    const float* kb = kk + (size_t)b * L_ * 64;
    const float* vb = v + (size_t)b * L_ * 64;
    const float* pb = pos + (size_t)b * P_ * 64;

    float* ring = (float*)(sm + O_G);
    float2* st = (float2*)(sm + O_ST);
    int* cnt = (int*)(sm + O_MC);

    // ---- mask dtype detection (first 8KB): byte-elems vs 4-byte-elems ----
    if (tid < 2) cnt[tid] = 0;
    __syncthreads();
    {
        int c0 = 0, c1 = 0;
        #pragma unroll
        for (int e = 0; e < 2; e++) {
            uint4 u = ((const uint4*)maskp)[tid * 2 + e];
            uint32_t ws[4] = {u.x, u.y, u.z, u.w};
            #pragma unroll
            for (int wdx = 0; wdx < 4; wdx++) {
                c0 += ((ws[wdx] & 0x000000ffu) != 0);
                c1 += ((ws[wdx] & 0x0000ff00u) != 0);
            }
        }
        if (c0) atomicAdd(&cnt[0], c0);
        if (c1) atomicAdd(&cnt[1], c1);
    }
    __syncthreads();
    const int mode = (cnt[0] > 0 && cnt[1] > 0) ? 0 : 1;   // 0 = bool bytes, 1 = 4B elems

    // ---- prologue loads: Q, R (scaled 1/8), P window 0, K tile 0 ----
    {
        const int r = tid & 63, cb = tid >> 6;
        #pragma unroll
        for (int e = 0; e < 4; e++) {
            float4 a = *(const float4*)(qb + (size_t)(l0 + r) * 64 + cb * 16 + 4 * e);
            a.x *= .125f; a.y *= .125f; a.z *= .125f; a.w *= .125f;
            spl(sm, O_QH, O_QL, r * SB + cb * 16 + 4 * e, a);
            float4 rr = *(const float4*)(qb + (size_t)(L_ - 1 - (l0 + r)) * 64 + cb * 16 + 4 * e);
            rr.x *= .125f; rr.y *= .125f; rr.z *= .125f; rr.w *= .125f;
            spl(sm, O_RH, O_RL, r * SB + cb * 16 + 4 * e, rr);
            float4 kv = *(const float4*)(kb + (size_t)r * 64 + cb * 16 + 4 * e);
            spl(sm, O_KH, O_KL, r * SB + cb * 16 + 4 * e, kv);
            int pr = l0 + r; if (pr > P_ - 1) pr = P_ - 1;
            float4 pv = *(const float4*)(pb + (size_t)pr * 64 + cb * 16 + 4 * e);
            spl(sm, O_PH, O_PL, r * SB + cb * 16 + 4 * e, pv);
        }
    }
    __syncthreads();

    // fragment address helpers
    auto adA = [&](int off, int kc) -> uint32_t {
        return sb + off + ((16 * wr + (lane & 15)) * SB + kc * 16 + (lane >> 4) * 8) * 2;
    };
    auto adB = [&](int off, int nf, int kc) -> uint32_t {
        return sb + off + ((32 * wc + 8 * nf + (lane & 7)) * SB + kc * 16 + ((lane >> 3) & 1) * 8) * 2;
    };
    auto adBT = [&](int off, int nf, int kc) -> uint32_t {
        return sb + off + ((kc * 16 + (lane & 15)) * SB + 32 * wc + 8 * nf) * 2;
    };
    // 3-product split-bf16 GEMM: acc += Ah*Bh + Al*Bh + Ah*Bl  (m16n32k64 per warp)
    auto gemm = [&](int oAh, int oAl, int oBh, int oBl, float acc[4][4]) {
        uint32_t Ah[4][4], Al[4][4];
        #pragma unroll
        for (int kc = 0; kc < 4; kc++) { LDSM4(Ah[kc], adA(oAh, kc)); LDSM4(Al[kc], adA(oAl, kc)); }
        #pragma unroll
        for (int nf = 0; nf < 4; nf++) {
            uint32_t Bf[2];
            #pragma unroll
            for (int kc = 0; kc < 4; kc++) {
                LDSM2(Bf, adB(oBh, nf, kc));
                MMA(acc[nf], Ah[kc], Bf);
                MMA(acc[nf], Al[kc], Bf);
            }
            #pragma unroll
            for (int kc = 0; kc < 4; kc++) {
                LDSM2(Bf, adB(oBl, nf, kc));
                MMA(acc[nf], Ah[kc], Bf);
            }
        }
    };

    const int r0 = 16 * wr + (lane >> 2), c2 = lane & 3;

    // ---- prologue G0 = R @ P(win0)^T -> ring[0] ----
    {
        float accG[4][4] = {};
        gemm(O_RH, O_RL, O_PH, O_PL, accG);
        __syncthreads();                       // all warps done reading P
        #pragma unroll
        for (int nf = 0; nf < 4; nf++) {
            int j0 = 32 * wc + 8 * nf + 2 * c2;
            #pragma unroll
            for (int h = 0; h < 2; h++) {
                int i = r0 + 8 * h;
                *(float2*)(ring + i * GS + j0) = make_float2(accG[nf][2 * h], accG[nf][2 * h + 1]);
            }
        }
        // load P window 1
        const int r = tid & 63, cb = tid >> 6;
        #pragma unroll
        for (int e = 0; e < 4; e++) {
            int pr = l0 + 64 + r; if (pr > P_ - 1) pr = P_ - 1;
            float4 pv = *(const float4*)(pb + (size_t)pr * 64 + cb * 16 + 4 * e);
            spl(sm, O_PH, O_PL, r * SB + cb * 16 + 4 * e, pv);
        }
        __syncthreads();
    }

    float run_m[2] = {-CUDART_INF_F, -CUDART_INF_F};
    float run_s[2] = {0.f, 0.f};

    // ================= phase 1: logits sweep =================
    for (int t = 0; t < NS; t++) {
        float accS[4][4] = {};
        float accG[4][4] = {};
        gemm(O_QH, O_QL, O_KH, O_KL, accS);
        gemm(O_RH, O_RL, O_PH, O_PL, accG);
        __syncthreads();                       // sync1: MMA reads of K/P complete
        // stash G_{t+1} into ring[(t+1)&1]
        {
            float* gn = ring + ((t + 1) & 1) * GSZ;
            #pragma unroll
            for (int nf = 0; nf < 4; nf++) {
                int j0 = 32 * wc + 8 * nf + 2 * c2;
                #pragma unroll
                for (int h = 0; h < 2; h++) {
                    int i = r0 + 8 * h;
                    *(float2*)(gn + i * GS + j0) = make_float2(accG[nf][2 * h], accG[nf][2 * h + 1]);
                }
            }
        }
        // load K_{t+1}, P window t+2
        {
            const int r = tid & 63, cb = tid >> 6;
            #pragma unroll
            for (int e = 0; e < 4; e++) {
                if (t < NS - 1) {
                    float4 kv = *(const float4*)(kb + (size_t)((t + 1) * 64 + r) * 64 + cb * 16 + 4 * e);
                    spl(sm, O_KH, O_KL, r * SB + cb * 16 + 4 * e, kv);
                }
                int pr = l0 + 64 * (t + 2) + r; if (pr > P_ - 1) pr = P_ - 1;
                float4 pv = *(const float4*)(pb + (size_t)pr * 64 + cb * 16 + 4 * e);
                spl(sm, O_PH, O_PL, r * SB + cb * 16 + 4 * e, pv);
            }
        }
        __syncthreads();                       // sync2: ring + new tiles visible
        // epilogue: bias + mask + stats + store logits
        const float* gc = ring + (t & 1) * GSZ;
        const float* gn = ring + ((t + 1) & 1) * GSZ;
        float xv[2][8];
        #pragma unroll
        for (int nf = 0; nf < 4; nf++) {
            int j0 = 32 * wc + 8 * nf + 2 * c2;
            #pragma unroll
            for (int h = 0; h < 2; h++) {
                int i = r0 + 8 * h;
                int s = i + j0;
                float b0 = ((s < 64) ? gc : gn)[i * GS + (s & 63)];
                float b1 = ((s + 1 < 64) ? gc : gn)[i * GS + ((s + 1) & 63)];
                float x0 = accS[nf][2 * h] + b0;
                float x1 = accS[nf][2 * h + 1] + b1;
                size_t gidx = ((size_t)b * L_ + l0 + i) * L_ + t * 64 + j0;
                if (mode == 0) {
                    unsigned short mv = *(const unsigned short*)(maskp + gidx);
                    if (mv & 0x00ff) x0 = -CUDART_INF_F;
                    if (mv & 0xff00) x1 = -CUDART_INF_F;
                } else {
                    uint2 mv = *(const uint2*)((const uint32_t*)maskp + gidx);
                    if (mv.x) x0 = -CUDART_INF_F;
                    if (mv.y) x1 = -CUDART_INF_F;
                }
                *(float2*)(attn + gidx) = make_float2(x0, x1);
                xv[h][2 * nf] = x0; xv[h][2 * nf + 1] = x1;
            }
        }
        #pragma unroll
        for (int h = 0; h < 2; h++) {
            float lm = xv[h][0];
            #pragma unroll
            for (int j = 1; j < 8; j++) lm = fmaxf(lm, xv[h][j]);
            float nm = fmaxf(run_m[h], lm);
            float base = (nm == -CUDART_INF_F) ? 0.f : nm;
            float es = 0.f;
            #pragma unroll
            for (int j = 0; j < 8; j++) es += __expf(xv[h][j] - base);
            run_s[h] = run_s[h] * __expf(run_m[h] - base) + es;
            run_m[h] = nm;
        }
    }

    // ---- merge stats: across quad lanes (shfl), then across wc warps (smem) ----
    #pragma unroll
    for (int h = 0; h < 2; h++) {
        #pragma unroll
        for (int sft = 1; sft < 4; sft <<= 1) {
            float om = __shfl_xor_sync(0xffffffffu, run_m[h], sft);
            float os = __shfl_xor_sync(0xffffffffu, run_s[h], sft);
            merge_ms(run_m[h], run_s[h], om, os);
        }
        if (c2 == 0) st[(r0 + 8 * h) * 2 + wc] = make_float2(run_m[h], run_s[h]);
    }
    __syncthreads();
    float mxu[2], inv[2];
    #pragma unroll
    for (int h = 0; h < 2; h++) {
        int i = r0 + 8 * h;
        float2 a = st[i * 2 + 0], bq = st[i * 2 + 1];
        float m = a.x, s = a.y;
        merge_ms(m, s, bq.x, bq.y);
        mxu[h] = (m == -CUDART_INF_F) ? 0.f : m;
        inv[h] = 1.f / s;
    }
    __syncthreads();

    // ================= phase 2: probs + O = P @ V =================
    float accO[4][4] = {};
    for (int t = 0; t < NS; t++) {
        // probs from own logits; write to attn and to smem P tiles (reuse Q bufs)
        #pragma unroll
        for (int nf = 0; nf < 4; nf++) {
            int j0 = 32 * wc + 8 * nf + 2 * c2;
            #pragma unroll
            for (int h = 0; h < 2; h++) {
                int i = r0 + 8 * h;
                size_t gidx = ((size_t)b * L_ + l0 + i) * L_ + t * 64 + j0;
                float2 x = *(const float2*)(attn + gidx);
                float p0 = __expf(x.x - mxu[h]) * inv[h];
                float p1 = __expf(x.y - mxu[h]) * inv[h];
                *(float2*)(attn + gidx) = make_float2(p0, p1);
                float h0 = __bfloat162float(__float2bfloat16(p0));
                float h1 = __bfloat162float(__float2bfloat16(p1));
                *(uint32_t*)(sm + O_QH + (i * SB + j0) * 2) = pk2(p0, p1);
                *(uint32_t*)(sm + O_QL + (i * SB + j0) * 2) = pk2(p0 - h0, p1 - h1);
            }
        }
        // V tile (natural [m][d] layout; fragment via ldmatrix.trans)
        {
            const int r = tid & 63, cb = tid >> 6;
            #pragma unroll
            for (int e = 0; e < 4; e++) {
                float4 vv = *(const float4*)(vb + (size_t)(t * 64 + r) * 64 + cb * 16 + 4 * e);
                spl(sm, O_KH, O_KL, r * SB + cb * 16 + 4 * e, vv);
            }
        }
        __syncthreads();
        // accO += P @ V  (3-product split)
        {
            uint32_t Ah[4][4], Al[4][4];
            #pragma unroll
            for (int kc = 0; kc < 4; kc++) { LDSM4(Ah[kc], adA(O_QH, kc)); LDSM4(Al[kc], adA(O_QL, kc)); }
            #pragma unroll
            for (int nf = 0; nf < 4; nf++) {
                uint32_t Bf[2];
                #pragma unroll
                for (int kc = 0; kc < 4; kc++) {
                    LDSM2T(Bf, adBT(O_KH, nf, kc));
                    MMA(accO[nf], Ah[kc], Bf);
                    MMA(accO[nf], Al[kc], Bf);
                }
                #pragma unroll
                for (int kc = 0; kc < 4; kc++) {
                    LDSM2T(Bf, adBT(O_KL, nf, kc));
                    MMA(accO[nf], Ah[kc], Bf);
                }
            }
        }
        __syncthreads();
    }
    // ---- store O ----
    #pragma unroll
    for (int nf = 0; nf < 4; nf++) {
        int j0 = 32 * wc + 8 * nf + 2 * c2;
        #pragma unroll
        for (int h = 0; h < 2; h++) {
            int i = r0 + 8 * h;
            *(float2*)(out + ((size_t)b * L_ + l0 + i) * 64 + j0) =
                make_float2(accO[nf][2 * h], accO[nf][2 * h + 1]);
        }
    }
}

extern "C" void kernel_launch(void* const* d_in, const int* in_sizes, int n_in,
                              void* d_out, int out_size) {
    const float* q = (const float*)d_in[0];
    const float* k = (const float*)d_in[1];
    const float* v = (const float*)d_in[2];
    const float* pos = (const float*)d_in[3];
    const char* msk = (const char*)d_in[4];
    float* out = (float*)d_out;
    float* attn = out + (size_t)B_ * L_ * 64;

    cudaFuncSetAttribute(fused_mma_kernel,
                         cudaFuncAttributeMaxDynamicSharedMemorySize, SMEMB);
    fused_mma_kernel<<<dim3(16, B_), 256, SMEMB>>>(q, k, v, pos, msk, out, attn);
}